// round 3
// baseline (speedup 1.0000x reference)
#include <cuda_runtime.h>
#include <math.h>

// ---------------------------------------------------------------------------
// Problem: B=4, N=4096, d_in=d_new=1024
//   Q = X@Wq + bq ; K = X@Wk + bk ; V = X@Wv + bv          (each [B*N, 1024])
//   S = (Q @ K^T) / sqrt(1024)                             ([B, N, N])
//   P = softmax_rows(S)
//   O = P @ V                                              ([B, N, 1024])
// ---------------------------------------------------------------------------

#define BATCH   4
#define SEQ     4096
#define DIM     1024
#define M_TOT   (BATCH * SEQ)          // 16384

// Scratch (device globals: allowed; no runtime allocation)
__device__ float g_Q[(size_t)M_TOT * DIM];
__device__ float g_K[(size_t)M_TOT * DIM];
__device__ float g_V[(size_t)M_TOT * DIM];
__device__ float g_S[(size_t)BATCH * SEQ * SEQ];

// ---------------------------------------------------------------------------
// Tiled SGEMM: C[M,N] = scale * (A[M,K] @ B) (+ bias[n])
//   TRANSB=0: B is row-major [K,N]  (element (k,n) = B[k*ldb + n])
//   TRANSB=1: B is row-major [N,K]  (element (k,n) = B[n*ldb + k])  -> Q@K^T
// 128x128 tile, BK=16, 256 threads, 8x8 per thread.
// ---------------------------------------------------------------------------
#define BM 128
#define BN 128
#define BK 16
#define SMPAD 4   // pad smem rows to 132 floats: kills transpose-store conflicts

template <bool TRANSB>
__global__ __launch_bounds__(256)
void sgemm_kernel(const float* __restrict__ A,
                  const float* __restrict__ B,
                  float*       __restrict__ C,
                  const float* __restrict__ bias,
                  int M, int N, int Kd,
                  int lda, int ldb, int ldc,
                  float scale,
                  long long strideA, long long strideB, long long strideC)
{
    __shared__ float As[BK][BM + SMPAD];
    __shared__ float Bs[BK][BN + SMPAD];

    const int bz = blockIdx.z;
    A += (size_t)bz * strideA;
    B += (size_t)bz * strideB;
    C += (size_t)bz * strideC;

    // NOTE: x -> M tile, y -> N tile (consecutive CTAs walk the M dimension,
    // sharing B-tiles in L2; same-y rows share A-tiles).
    const int m0 = blockIdx.x * BM;
    const int n0 = blockIdx.y * BN;

    const int tid = threadIdx.x;
    const int tx  = tid & 15;          // 0..15  -> n micro
    const int ty  = tid >> 4;          // 0..15  -> m micro

    // A-style loader (also used for TRANSB B tile): 128 rows x 16 k
    const int arow = tid >> 2;         // 0..63
    const int acol = (tid & 3) * 4;    // 0,4,8,12
    // B no-trans loader: 16 k-rows x 128 n
    const int brow = tid >> 5;         // 0..7
    const int bcol = (tid & 31) * 4;   // 0..124

    float acc[8][8];
    #pragma unroll
    for (int i = 0; i < 8; ++i)
        #pragma unroll
        for (int j = 0; j < 8; ++j) acc[i][j] = 0.0f;

    for (int k0 = 0; k0 < Kd; k0 += BK) {
        // ---- load A tile (transpose into [k][m]) ----
        #pragma unroll
        for (int r = 0; r < 2; ++r) {
            const int row = arow + r * 64;
            const float4 v = *(const float4*)(A + (size_t)(m0 + row) * lda + k0 + acol);
            As[acol + 0][row] = v.x;
            As[acol + 1][row] = v.y;
            As[acol + 2][row] = v.z;
            As[acol + 3][row] = v.w;
        }
        // ---- load B tile ----
        if (TRANSB) {
            #pragma unroll
            for (int r = 0; r < 2; ++r) {
                const int row = arow + r * 64;   // n index
                const float4 v = *(const float4*)(B + (size_t)(n0 + row) * ldb + k0 + acol);
                Bs[acol + 0][row] = v.x;
                Bs[acol + 1][row] = v.y;
                Bs[acol + 2][row] = v.z;
                Bs[acol + 3][row] = v.w;
            }
        } else {
            #pragma unroll
            for (int r = 0; r < 2; ++r) {
                const int row = brow + r * 8;    // k index
                const float4 v = *(const float4*)(B + (size_t)(k0 + row) * ldb + n0 + bcol);
                *(float4*)&Bs[row][bcol] = v;
            }
        }
        __syncthreads();

        // ---- compute ----
        #pragma unroll
        for (int kk = 0; kk < BK; ++kk) {
            float a[8], b[8];
            *(float4*)(a)     = *(const float4*)&As[kk][ty * 8];
            *(float4*)(a + 4) = *(const float4*)&As[kk][ty * 8 + 4];
            *(float4*)(b)     = *(const float4*)&Bs[kk][tx * 8];
            *(float4*)(b + 4) = *(const float4*)&Bs[kk][tx * 8 + 4];
            #pragma unroll
            for (int i = 0; i < 8; ++i)
                #pragma unroll
                for (int j = 0; j < 8; ++j)
                    acc[i][j] = fmaf(a[i], b[j], acc[i][j]);
        }
        __syncthreads();
    }

    // ---- epilogue: scale, +bias, store ----
    #pragma unroll
    for (int i = 0; i < 8; ++i) {
        const int m = m0 + ty * 8 + i;
        #pragma unroll
        for (int j = 0; j < 8; j += 4) {
            const int n = n0 + tx * 8 + j;
            float4 v;
            v.x = acc[i][j + 0] * scale;
            v.y = acc[i][j + 1] * scale;
            v.z = acc[i][j + 2] * scale;
            v.w = acc[i][j + 3] * scale;
            if (bias) {
                v.x += bias[n + 0];
                v.y += bias[n + 1];
                v.z += bias[n + 2];
                v.w += bias[n + 3];
            }
            *(float4*)(C + (size_t)m * ldc + n) = v;
        }
    }
}

// ---------------------------------------------------------------------------
// Row softmax over 4096-wide rows, in place. 256 threads, 16 values/thread
// kept in registers (one global read + one global write per element).
// ---------------------------------------------------------------------------
__global__ __launch_bounds__(256)
void softmax_kernel(float* __restrict__ S)
{
    float* p = S + (size_t)blockIdx.x * SEQ;
    const int tid = threadIdx.x;

    float v[16];
    float mx = -INFINITY;
    #pragma unroll
    for (int i = 0; i < 16; ++i) {
        v[i] = p[tid + i * 256];
        mx = fmaxf(mx, v[i]);
    }
    #pragma unroll
    for (int o = 16; o > 0; o >>= 1)
        mx = fmaxf(mx, __shfl_xor_sync(0xFFFFFFFFu, mx, o));

    __shared__ float redmx[8];
    __shared__ float redsm[8];
    if ((tid & 31) == 0) redmx[tid >> 5] = mx;
    __syncthreads();
    mx = redmx[0];
    #pragma unroll
    for (int w = 1; w < 8; ++w) mx = fmaxf(mx, redmx[w]);

    float sum = 0.0f;
    #pragma unroll
    for (int i = 0; i < 16; ++i) {
        v[i] = __expf(v[i] - mx);
        sum += v[i];
    }
    #pragma unroll
    for (int o = 16; o > 0; o >>= 1)
        sum += __shfl_xor_sync(0xFFFFFFFFu, sum, o);
    if ((tid & 31) == 0) redsm[tid >> 5] = sum;
    __syncthreads();
    sum = 0.0f;
    #pragma unroll
    for (int w = 0; w < 8; ++w) sum += redsm[w];

    const float inv = 1.0f / sum;
    #pragma unroll
    for (int i = 0; i < 16; ++i)
        p[tid + i * 256] = v[i] * inv;
}

// ---------------------------------------------------------------------------
// Launch
// ---------------------------------------------------------------------------
extern "C" void kernel_launch(void* const* d_in, const int* in_sizes, int n_in,
                              void* d_out, int out_size)
{
    const float* X  = (const float*)d_in[0];
    const float* Wq = (const float*)d_in[1];
    const float* Wk = (const float*)d_in[2];
    const float* Wv = (const float*)d_in[3];
    const float* bq = (const float*)d_in[4];
    const float* bk = (const float*)d_in[5];
    const float* bv = (const float*)d_in[6];
    float* O = (float*)d_out;

    float *Qp, *Kp, *Vp, *Sp;
    cudaGetSymbolAddress((void**)&Qp, g_Q);
    cudaGetSymbolAddress((void**)&Kp, g_K);
    cudaGetSymbolAddress((void**)&Vp, g_V);
    cudaGetSymbolAddress((void**)&Sp, g_S);

    const float inv_sqrt_d = 1.0f / 32.0f;   // 1/sqrt(1024)

    // 1) QKV projections: [16384,1024] @ [1024,1024] + bias
    {
        dim3 grid(M_TOT / BM, DIM / BN, 1);
        sgemm_kernel<false><<<grid, 256>>>(X, Wq, Qp, bq, M_TOT, DIM, DIM,
                                           DIM, DIM, DIM, 1.0f, 0, 0, 0);
        sgemm_kernel<false><<<grid, 256>>>(X, Wk, Kp, bk, M_TOT, DIM, DIM,
                                           DIM, DIM, DIM, 1.0f, 0, 0, 0);
        sgemm_kernel<false><<<grid, 256>>>(X, Wv, Vp, bv, M_TOT, DIM, DIM,
                                           DIM, DIM, DIM, 1.0f, 0, 0, 0);
    }

    // 2) S = scale * Q @ K^T   (batched over z)
    {
        dim3 grid(SEQ / BM, SEQ / BN, BATCH);
        sgemm_kernel<true><<<grid, 256>>>(Qp, Kp, Sp, nullptr, SEQ, SEQ, DIM,
                                          DIM, DIM, SEQ, inv_sqrt_d,
                                          (long long)SEQ * DIM,
                                          (long long)SEQ * DIM,
                                          (long long)SEQ * SEQ);
    }

    // 3) row softmax, in place
    softmax_kernel<<<BATCH * SEQ, 256>>>(Sp);

    // 4) O = P @ V
    {
        dim3 grid(SEQ / BM, DIM / BN, BATCH);
        sgemm_kernel<false><<<grid, 256>>>(Sp, Vp, O, nullptr, SEQ, DIM, SEQ,
                                           SEQ, DIM, DIM, 1.0f,
                                           (long long)SEQ * SEQ,
                                           (long long)SEQ * DIM,
                                           (long long)SEQ * DIM);
    }
}

// round 5
// speedup vs baseline: 2.7047x; 2.7047x over previous
#include <cuda_runtime.h>
#include <cuda_bf16.h>
#include <math.h>

// ===========================================================================
// SelfAttention B=4, N=4096, d=1024 — bf16 split-precision mma.sync pipeline
// (baseline sm_100: no tcgen05/TMA; HMMA via mma.sync.m16n8k16 + ldmatrix)
//   split:  x = hi(bf16) + lo(bf16);  A*B ~= AhBh + AlBh + AhBl  (fp32 acc)
// ===========================================================================

#define BATCH 4
#define SEQ   4096
#define DIM   1024
#define M_TOT (BATCH*SEQ)

// ------------------------------ scratch -----------------------------------
__device__ __align__(128) __nv_bfloat16 g_Xh[(size_t)M_TOT * DIM];
__device__ __align__(128) __nv_bfloat16 g_Xl[(size_t)M_TOT * DIM];
__device__ __align__(128) __nv_bfloat16 g_Wth[3][(size_t)DIM * DIM];
__device__ __align__(128) __nv_bfloat16 g_Wtl[3][(size_t)DIM * DIM];
__device__ __align__(128) __nv_bfloat16 g_Qh[(size_t)M_TOT * DIM];
__device__ __align__(128) __nv_bfloat16 g_Ql[(size_t)M_TOT * DIM];
__device__ __align__(128) __nv_bfloat16 g_Kh[(size_t)M_TOT * DIM];
__device__ __align__(128) __nv_bfloat16 g_Kl[(size_t)M_TOT * DIM];
__device__ __align__(128) __nv_bfloat16 g_Vth[(size_t)BATCH * DIM * SEQ];
__device__ __align__(128) __nv_bfloat16 g_Vtl[(size_t)BATCH * DIM * SEQ];
__device__ __align__(128) float         g_S [(size_t)BATCH * SEQ * SEQ];
__device__ __align__(128) __nv_bfloat16 g_Ph[(size_t)BATCH * SEQ * SEQ];
__device__ __align__(128) __nv_bfloat16 g_Pl[(size_t)BATCH * SEQ * SEQ];

// ------------------------------ helpers ------------------------------------
static __device__ __forceinline__ unsigned smem_u32(const void* p) {
    unsigned r;
    asm("{ .reg .u64 t; cvta.to.shared.u64 t, %1; cvt.u32.u64 %0, t; }"
        : "=r"(r) : "l"(p));
    return r;
}
// SW64 swizzle: 64B rows, XOR 16B-chunk bits[4:5] with row bits[7:8]
static __device__ __forceinline__ unsigned swz(unsigned o) {
    return o ^ ((o >> 3) & 0x30);
}
static __device__ __forceinline__ void bsplit(float v, unsigned short& h, unsigned short& l) {
    __nv_bfloat16 hb = __float2bfloat16_rn(v);
    __nv_bfloat16 lb = __float2bfloat16_rn(v - __bfloat162float(hb));
    h = __bfloat16_as_ushort(hb);
    l = __bfloat16_as_ushort(lb);
}
static __device__ __forceinline__ void ldm_x4(unsigned& r0, unsigned& r1,
                                              unsigned& r2, unsigned& r3, unsigned a) {
    asm volatile("ldmatrix.sync.aligned.m8n8.x4.shared.b16 {%0,%1,%2,%3}, [%4];"
                 : "=r"(r0), "=r"(r1), "=r"(r2), "=r"(r3) : "r"(a));
}
static __device__ __forceinline__ void mma16816(float* c, const unsigned* a, const unsigned* b) {
    asm volatile("mma.sync.aligned.m16n8k16.row.col.f32.bf16.bf16.f32 "
                 "{%0,%1,%2,%3}, {%4,%5,%6,%7}, {%8,%9}, {%0,%1,%2,%3};"
                 : "+f"(c[0]), "+f"(c[1]), "+f"(c[2]), "+f"(c[3])
                 : "r"(a[0]), "r"(a[1]), "r"(a[2]), "r"(a[3]), "r"(b[0]), "r"(b[1]));
}
#define CP16(dst, src) \
    asm volatile("cp.async.cg.shared.global [%0], [%1], 16;" :: "r"(dst), "l"(src) : "memory")

// ------------------------------ GEMM ---------------------------------------
// CTA 128x128, BK=32, 3 stages. smem per stage: Ah|Al|Bh|Bl, 8KB each.
#define BKW     32
#define TBYTES  8192                  // 128 * 32 * 2
#define STG_B   (4 * TBYTES)          // 32768
#define STAGES  3
#define GEMM_SMEM (STAGES * STG_B)    // 98304

// one 128x32 bf16 tile, K-major rows, SW64-swizzled; 256 threads, 2x16B each
static __device__ __forceinline__ void load_tile(unsigned dst,
        const __nv_bfloat16* __restrict__ src, int ld, int tid)
{
    #pragma unroll
    for (int it = 0; it < 2; ++it) {
        const int s = tid + it * 256;
        const int row = s >> 2, ch = s & 3;
        const unsigned off = swz((unsigned)(row * 64 + ch * 16));
        const char* g = (const char*)(src + (size_t)row * ld) + ch * 16;
        CP16(dst + off, g);
    }
}

// MODE 0: out = acc+bias -> split bf16 row-major (Q,K)
// MODE 1: out = acc+bias -> split bf16 transposed [e][seq] (V)
// MODE 2: out = acc*scale -> fp32 row-major (S, O)
template <int MODE>
__global__ __launch_bounds__(256, 1)
void gemm_bf16x3(const __nv_bfloat16* __restrict__ Ah, const __nv_bfloat16* __restrict__ Al,
                 const __nv_bfloat16* __restrict__ Bh, const __nv_bfloat16* __restrict__ Bl,
                 int lda, int ldb, long long sA, long long sB, int Kd,
                 const float* __restrict__ bias, float scale,
                 float* __restrict__ out32, int ldc, long long sC,
                 __nv_bfloat16* __restrict__ outh, __nv_bfloat16* __restrict__ outl)
{
    extern __shared__ __align__(128) char smem[];
    const unsigned sbase = smem_u32(smem);
    const int tid = threadIdx.x;
    const int bz  = blockIdx.z;

    Ah += (size_t)bz * sA;  Al += (size_t)bz * sA;
    Bh += (size_t)bz * sB;  Bl += (size_t)bz * sB;

    const int m0 = blockIdx.x * 128;
    const int n0 = blockIdx.y * 128;

    const __nv_bfloat16* a_h = Ah + (size_t)m0 * lda;
    const __nv_bfloat16* a_l = Al + (size_t)m0 * lda;
    const __nv_bfloat16* b_h = Bh + (size_t)n0 * ldb;
    const __nv_bfloat16* b_l = Bl + (size_t)n0 * ldb;

    const int lane = tid & 31;
    const int w    = tid >> 5;
    const int wm   = w & 1;         // 2 warps in M (64 rows each)
    const int wn   = w >> 1;        // 4 warps in N (32 cols each)

    // ldmatrix per-lane base offsets (pre-swizzle)
    const unsigned aoff = ((unsigned)(wm * 64 + (lane & 15)) << 6) + ((unsigned)(lane >> 4) << 4);
    const unsigned boff = ((unsigned)(wn * 32 + ((lane >> 4) << 3) + (lane & 7)) << 6)
                        + ((unsigned)((lane >> 3) & 1) << 4);

    float acc[4][4][4];
    #pragma unroll
    for (int i = 0; i < 4; ++i)
        #pragma unroll
        for (int j = 0; j < 4; ++j)
            #pragma unroll
            for (int q = 0; q < 4; ++q) acc[i][j][q] = 0.0f;

    const int NC = Kd / BKW;

    // prologue: stages 0,1
    #pragma unroll
    for (int p = 0; p < 2; ++p) {
        const unsigned sb = sbase + p * STG_B;
        const int k0 = p * BKW;
        load_tile(sb,              a_h + k0, lda, tid);
        load_tile(sb + TBYTES,     a_l + k0, lda, tid);
        load_tile(sb + 2 * TBYTES, b_h + k0, ldb, tid);
        load_tile(sb + 3 * TBYTES, b_l + k0, ldb, tid);
        asm volatile("cp.async.commit_group;" ::: "memory");
    }

    for (int c = 0; c < NC; ++c) {
        if (c + 1 < NC)
            asm volatile("cp.async.wait_group %0;" :: "n"(1) : "memory");
        else
            asm volatile("cp.async.wait_group %0;" :: "n"(0) : "memory");
        __syncthreads();

        if (c + 2 < NC) {
            const unsigned sb = sbase + ((c + 2) % STAGES) * STG_B;
            const int k0 = (c + 2) * BKW;
            load_tile(sb,              a_h + k0, lda, tid);
            load_tile(sb + TBYTES,     a_l + k0, lda, tid);
            load_tile(sb + 2 * TBYTES, b_h + k0, ldb, tid);
            load_tile(sb + 3 * TBYTES, b_l + k0, ldb, tid);
            asm volatile("cp.async.commit_group;" ::: "memory");
        }

        const unsigned sb = sbase + (c % STAGES) * STG_B;
        #pragma unroll
        for (int ks = 0; ks < 2; ++ks) {
            unsigned Afh[4][4], Afl[4][4], Bfh[4][2], Bfl[4][2];
            #pragma unroll
            for (int mt = 0; mt < 4; ++mt) {
                const unsigned o = swz(aoff + (mt << 10) + (ks << 5));
                ldm_x4(Afh[mt][0], Afh[mt][1], Afh[mt][2], Afh[mt][3], sb + o);
                ldm_x4(Afl[mt][0], Afl[mt][1], Afl[mt][2], Afl[mt][3], sb + TBYTES + o);
            }
            #pragma unroll
            for (int jp = 0; jp < 2; ++jp) {
                const unsigned o = swz(boff + (jp << 10) + (ks << 5));
                ldm_x4(Bfh[2*jp][0], Bfh[2*jp][1], Bfh[2*jp+1][0], Bfh[2*jp+1][1],
                       sb + 2 * TBYTES + o);
                ldm_x4(Bfl[2*jp][0], Bfl[2*jp][1], Bfl[2*jp+1][0], Bfl[2*jp+1][1],
                       sb + 3 * TBYTES + o);
            }
            #pragma unroll
            for (int mt = 0; mt < 4; ++mt)
                #pragma unroll
                for (int nt = 0; nt < 4; ++nt) {
                    mma16816(acc[mt][nt], Afh[mt], Bfh[nt]);
                    mma16816(acc[mt][nt], Afl[mt], Bfh[nt]);
                    mma16816(acc[mt][nt], Afh[mt], Bfl[nt]);
                }
        }
    }

    // ------------------------------ epilogue -------------------------------
    const int g  = lane >> 2;            // row within 8
    const int tg = lane & 3;             // col pair
    #pragma unroll
    for (int mt = 0; mt < 4; ++mt) {
        #pragma unroll
        for (int nt = 0; nt < 4; ++nt) {
            const int nb = n0 + wn * 32 + nt * 8 + 2 * tg;
            const int mb = m0 + wm * 64 + mt * 16 + g;
            float v0 = acc[mt][nt][0], v1 = acc[mt][nt][1];
            float v2 = acc[mt][nt][2], v3 = acc[mt][nt][3];
            if (MODE == 2) {
                float* d0 = out32 + (size_t)bz * sC + (size_t)mb * ldc + nb;
                float* d1 = out32 + (size_t)bz * sC + (size_t)(mb + 8) * ldc + nb;
                *(float2*)d0 = make_float2(v0 * scale, v1 * scale);
                *(float2*)d1 = make_float2(v2 * scale, v3 * scale);
            } else {
                const float b0 = bias[nb], b1 = bias[nb + 1];
                unsigned short h0, l0, h1, l1, h2, l2, h3, l3;
                bsplit(v0 + b0, h0, l0); bsplit(v1 + b1, h1, l1);
                bsplit(v2 + b0, h2, l2); bsplit(v3 + b1, h3, l3);
                if (MODE == 0) {
                    const size_t o0 = (size_t)mb * ldc + nb;
                    const size_t o1 = (size_t)(mb + 8) * ldc + nb;
                    *(unsigned*)(outh + o0) = ((unsigned)h1 << 16) | h0;
                    *(unsigned*)(outl + o0) = ((unsigned)l1 << 16) | l0;
                    *(unsigned*)(outh + o1) = ((unsigned)h3 << 16) | h2;
                    *(unsigned*)(outl + o1) = ((unsigned)l3 << 16) | l2;
                } else {            // MODE 1: transposed [e][seq]
                    const int b2 = mb >> 12;
                    const int s0 = mb & (SEQ - 1);
                    const size_t base = (size_t)b2 * DIM * SEQ;
                    outh[base + (size_t)nb * SEQ + s0]           = __ushort_as_bfloat16(h0);
                    outl[base + (size_t)nb * SEQ + s0]           = __ushort_as_bfloat16(l0);
                    outh[base + (size_t)(nb + 1) * SEQ + s0]     = __ushort_as_bfloat16(h1);
                    outl[base + (size_t)(nb + 1) * SEQ + s0]     = __ushort_as_bfloat16(l1);
                    outh[base + (size_t)nb * SEQ + s0 + 8]       = __ushort_as_bfloat16(h2);
                    outl[base + (size_t)nb * SEQ + s0 + 8]       = __ushort_as_bfloat16(l2);
                    outh[base + (size_t)(nb + 1) * SEQ + s0 + 8] = __ushort_as_bfloat16(h3);
                    outl[base + (size_t)(nb + 1) * SEQ + s0 + 8] = __ushort_as_bfloat16(l3);
                }
            }
        }
    }
}

// ------------------------- conversion kernels ------------------------------
__global__ __launch_bounds__(256)
void split_f32_kernel(const float* __restrict__ x,
                      __nv_bfloat16* __restrict__ h, __nv_bfloat16* __restrict__ l)
{
    const size_t i = (size_t)blockIdx.x * 256 + threadIdx.x;
    const float4 v = ((const float4*)x)[i];
    unsigned short h0, l0, h1, l1, h2, l2, h3, l3;
    bsplit(v.x, h0, l0); bsplit(v.y, h1, l1); bsplit(v.z, h2, l2); bsplit(v.w, h3, l3);
    ((uint2*)h)[i] = make_uint2(((unsigned)h1 << 16) | h0, ((unsigned)h3 << 16) | h2);
    ((uint2*)l)[i] = make_uint2(((unsigned)l1 << 16) | l0, ((unsigned)l3 << 16) | l2);
}

__global__ __launch_bounds__(256)
void transpose_split_kernel(const float* __restrict__ W,
                            __nv_bfloat16* __restrict__ Th, __nv_bfloat16* __restrict__ Tl)
{
    __shared__ float t[32][33];
    const int k0 = blockIdx.x * 32, n0 = blockIdx.y * 32;
    const int c = threadIdx.x & 31, r0 = threadIdx.x >> 5;
    #pragma unroll
    for (int i = 0; i < 4; ++i)
        t[r0 + i * 8][c] = W[(size_t)(k0 + r0 + i * 8) * DIM + n0 + c];
    __syncthreads();
    #pragma unroll
    for (int i = 0; i < 4; ++i) {
        const int r = r0 + i * 8;
        unsigned short h, l;
        bsplit(t[c][r], h, l);                  // = W[k0+c][n0+r]
        const size_t o = (size_t)(n0 + r) * DIM + k0 + c;
        Th[o] = __ushort_as_bfloat16(h);
        Tl[o] = __ushort_as_bfloat16(l);
    }
}

// ------------------------------ softmax ------------------------------------
__global__ __launch_bounds__(256)
void softmax_split_kernel(const float* __restrict__ S,
                          __nv_bfloat16* __restrict__ Ph, __nv_bfloat16* __restrict__ Pl)
{
    const float* p = S + (size_t)blockIdx.x * SEQ;
    const int tid = threadIdx.x;

    float4 v[4];
    float mx = -INFINITY;
    #pragma unroll
    for (int i = 0; i < 4; ++i) {
        v[i] = ((const float4*)p)[tid + i * 256];
        mx = fmaxf(mx, fmaxf(fmaxf(v[i].x, v[i].y), fmaxf(v[i].z, v[i].w)));
    }
    #pragma unroll
    for (int o = 16; o > 0; o >>= 1)
        mx = fmaxf(mx, __shfl_xor_sync(0xFFFFFFFFu, mx, o));

    __shared__ float redmx[8], redsm[8];
    if ((tid & 31) == 0) redmx[tid >> 5] = mx;
    __syncthreads();
    mx = redmx[0];
    #pragma unroll
    for (int w = 1; w < 8; ++w) mx = fmaxf(mx, redmx[w]);

    float sum = 0.0f;
    #pragma unroll
    for (int i = 0; i < 4; ++i) {
        v[i].x = __expf(v[i].x - mx); v[i].y = __expf(v[i].y - mx);
        v[i].z = __expf(v[i].z - mx); v[i].w = __expf(v[i].w - mx);
        sum += (v[i].x + v[i].y) + (v[i].z + v[i].w);
    }
    #pragma unroll
    for (int o = 16; o > 0; o >>= 1)
        sum += __shfl_xor_sync(0xFFFFFFFFu, sum, o);
    if ((tid & 31) == 0) redsm[tid >> 5] = sum;
    __syncthreads();
    sum = 0.0f;
    #pragma unroll
    for (int w = 0; w < 8; ++w) sum += redsm[w];
    const float inv = 1.0f / sum;

    #pragma unroll
    for (int i = 0; i < 4; ++i) {
        unsigned short h0, l0, h1, l1, h2, l2, h3, l3;
        bsplit(v[i].x * inv, h0, l0); bsplit(v[i].y * inv, h1, l1);
        bsplit(v[i].z * inv, h2, l2); bsplit(v[i].w * inv, h3, l3);
        const size_t q = (size_t)blockIdx.x * (SEQ / 4) + tid + i * 256;
        ((uint2*)Ph)[q] = make_uint2(((unsigned)h1 << 16) | h0, ((unsigned)h3 << 16) | h2);
        ((uint2*)Pl)[q] = make_uint2(((unsigned)l1 << 16) | l0, ((unsigned)l3 << 16) | l2);
    }
}

// ------------------------------ launch -------------------------------------
extern "C" void kernel_launch(void* const* d_in, const int* in_sizes, int n_in,
                              void* d_out, int out_size)
{
    const float* X  = (const float*)d_in[0];
    const float* Wq = (const float*)d_in[1];
    const float* Wk = (const float*)d_in[2];
    const float* Wv = (const float*)d_in[3];
    const float* bq = (const float*)d_in[4];
    const float* bk = (const float*)d_in[5];
    const float* bv = (const float*)d_in[6];
    float* O = (float*)d_out;

    __nv_bfloat16 *Xh, *Xl, *Wth, *Wtl, *Qh, *Ql, *Kh, *Kl, *Vth, *Vtl, *Ph, *Pl;
    float* S;
    cudaGetSymbolAddress((void**)&Xh,  g_Xh);
    cudaGetSymbolAddress((void**)&Xl,  g_Xl);
    cudaGetSymbolAddress((void**)&Wth, g_Wth);
    cudaGetSymbolAddress((void**)&Wtl, g_Wtl);
    cudaGetSymbolAddress((void**)&Qh,  g_Qh);
    cudaGetSymbolAddress((void**)&Ql,  g_Ql);
    cudaGetSymbolAddress((void**)&Kh,  g_Kh);
    cudaGetSymbolAddress((void**)&Kl,  g_Kl);
    cudaGetSymbolAddress((void**)&Vth, g_Vth);
    cudaGetSymbolAddress((void**)&Vtl, g_Vtl);
    cudaGetSymbolAddress((void**)&S,   g_S);
    cudaGetSymbolAddress((void**)&Ph,  g_Ph);
    cudaGetSymbolAddress((void**)&Pl,  g_Pl);

    cudaFuncSetAttribute(gemm_bf16x3<0>, cudaFuncAttributeMaxDynamicSharedMemorySize, GEMM_SMEM);
    cudaFuncSetAttribute(gemm_bf16x3<1>, cudaFuncAttributeMaxDynamicSharedMemorySize, GEMM_SMEM);
    cudaFuncSetAttribute(gemm_bf16x3<2>, cudaFuncAttributeMaxDynamicSharedMemorySize, GEMM_SMEM);

    const size_t DD = (size_t)DIM * DIM;

    // 0) conversions
    split_f32_kernel<<<(M_TOT * DIM) / (4 * 256), 256>>>(X, Xh, Xl);
    transpose_split_kernel<<<dim3(32, 32), 256>>>(Wq, Wth + 0 * DD, Wtl + 0 * DD);
    transpose_split_kernel<<<dim3(32, 32), 256>>>(Wk, Wth + 1 * DD, Wtl + 1 * DD);
    transpose_split_kernel<<<dim3(32, 32), 256>>>(Wv, Wth + 2 * DD, Wtl + 2 * DD);

    // 1) projections: [16384,1024] x Wt[n][k]
    {
        dim3 g(M_TOT / 128, DIM / 128, 1);       // (128, 8)
        gemm_bf16x3<0><<<g, 256, GEMM_SMEM>>>(Xh, Xl, Wth + 0 * DD, Wtl + 0 * DD,
            DIM, DIM, 0, 0, DIM, bq, 1.0f, nullptr, DIM, 0, Qh, Ql);
        gemm_bf16x3<0><<<g, 256, GEMM_SMEM>>>(Xh, Xl, Wth + 1 * DD, Wtl + 1 * DD,
            DIM, DIM, 0, 0, DIM, bk, 1.0f, nullptr, DIM, 0, Kh, Kl);
        gemm_bf16x3<1><<<g, 256, GEMM_SMEM>>>(Xh, Xl, Wth + 2 * DD, Wtl + 2 * DD,
            DIM, DIM, 0, 0, DIM, bv, 1.0f, nullptr, DIM, 0, Vth, Vtl);
    }

    // 2) S = (Q K^T)/32
    {
        dim3 g(SEQ / 128, SEQ / 128, BATCH);     // (32, 32, 4)
        gemm_bf16x3<2><<<g, 256, GEMM_SMEM>>>(Qh, Ql, Kh, Kl,
            DIM, DIM, (long long)SEQ * DIM, (long long)SEQ * DIM, DIM,
            nullptr, 1.0f / 32.0f, S, SEQ, (long long)SEQ * SEQ, nullptr, nullptr);
    }

    // 3) softmax rows -> split P
    softmax_split_kernel<<<BATCH * SEQ, 256>>>(S, Ph, Pl);

    // 4) O = P V
    {
        dim3 g(SEQ / 128, DIM / 128, BATCH);     // (32, 8, 4)
        gemm_bf16x3<2><<<g, 256, GEMM_SMEM>>>(Ph, Pl, Vth, Vtl,
            SEQ, SEQ, (long long)SEQ * SEQ, (long long)DIM * SEQ, SEQ,
            nullptr, 1.0f, O, DIM, (long long)SEQ * DIM, nullptr, nullptr);
    }
}

// round 6
// speedup vs baseline: 3.4131x; 1.2619x over previous
#include <cuda_runtime.h>
#include <cuda_fp16.h>
#include <math.h>

// ===========================================================================
// SelfAttention B=4, N=4096, d=1024 — fp16 split-precision mma.sync pipeline
//   split: x = h(fp16) + l(fp16);  A*B ~= Ah*Bh + Al*Bh   (2 passes, fp32 acc)
//   B-side operands (W, K, V) stored hi-only; dropped Ah*Bl term ~ 2^-12 rel.
// ===========================================================================

#define BATCH 4
#define SEQ   4096
#define DIM   1024
#define M_TOT (BATCH*SEQ)

// ------------------------------ scratch -----------------------------------
__device__ __align__(128) __half g_Xh[(size_t)M_TOT * DIM];
__device__ __align__(128) __half g_Xl[(size_t)M_TOT * DIM];
__device__ __align__(128) __half g_Wt[3][(size_t)DIM * DIM];
__device__ __align__(128) __half g_Qh[(size_t)M_TOT * DIM];
__device__ __align__(128) __half g_Ql[(size_t)M_TOT * DIM];
__device__ __align__(128) __half g_Kh[(size_t)M_TOT * DIM];
__device__ __align__(128) __half g_Vt[(size_t)BATCH * DIM * SEQ];
__device__ __align__(128) float  g_S [(size_t)BATCH * SEQ * SEQ];
__device__ __align__(128) __half g_Ph[(size_t)BATCH * SEQ * SEQ];
__device__ __align__(128) __half g_Pl[(size_t)BATCH * SEQ * SEQ];

// ------------------------------ helpers ------------------------------------
static __device__ __forceinline__ unsigned smem_u32(const void* p) {
    unsigned r;
    asm("{ .reg .u64 t; cvta.to.shared.u64 t, %1; cvt.u32.u64 %0, t; }"
        : "=r"(r) : "l"(p));
    return r;
}
// SW64 swizzle: 64B rows, XOR 16B-chunk bits[4:5] with row bits[7:8]
static __device__ __forceinline__ unsigned swz(unsigned o) {
    return o ^ ((o >> 3) & 0x30);
}
static __device__ __forceinline__ void hsplit(float v, unsigned short& h, unsigned short& l) {
    __half hb = __float2half_rn(v);
    __half lb = __float2half_rn(v - __half2float(hb));
    h = __half_as_ushort(hb);
    l = __half_as_ushort(lb);
}
static __device__ __forceinline__ unsigned short hhi(float v) {
    return __half_as_ushort(__float2half_rn(v));
}
static __device__ __forceinline__ void ldm_x4(unsigned& r0, unsigned& r1,
                                              unsigned& r2, unsigned& r3, unsigned a) {
    asm volatile("ldmatrix.sync.aligned.m8n8.x4.shared.b16 {%0,%1,%2,%3}, [%4];"
                 : "=r"(r0), "=r"(r1), "=r"(r2), "=r"(r3) : "r"(a));
}
static __device__ __forceinline__ void mma16816(float* c, const unsigned* a, const unsigned* b) {
    asm volatile("mma.sync.aligned.m16n8k16.row.col.f32.f16.f16.f32 "
                 "{%0,%1,%2,%3}, {%4,%5,%6,%7}, {%8,%9}, {%0,%1,%2,%3};"
                 : "+f"(c[0]), "+f"(c[1]), "+f"(c[2]), "+f"(c[3])
                 : "r"(a[0]), "r"(a[1]), "r"(a[2]), "r"(a[3]), "r"(b[0]), "r"(b[1]));
}
#define CP16(dst, src) \
    asm volatile("cp.async.cg.shared.global [%0], [%1], 16;" :: "r"(dst), "l"(src) : "memory")

// ------------------------------ GEMM ---------------------------------------
// CTA 128x128, BK=32, 4 stages. smem per stage: Ah|Al|Bh, 8KB each.
#define BKW     32
#define TBYTES  8192                  // 128 * 32 * 2
#define STG_B   (3 * TBYTES)          // 24576
#define STAGES  4
#define GEMM_SMEM (STAGES * STG_B)    // 98304

// one 128x32 fp16 tile, K-major rows, SW64-swizzled; 256 threads, 2x16B each
static __device__ __forceinline__ void load_tile(unsigned dst,
        const __half* __restrict__ src, int ld, int tid)
{
    #pragma unroll
    for (int it = 0; it < 2; ++it) {
        const int s = tid + it * 256;
        const int row = s >> 2, ch = s & 3;
        const unsigned off = swz((unsigned)(row * 64 + ch * 16));
        const char* g = (const char*)(src + (size_t)row * ld) + ch * 16;
        CP16(dst + off, g);
    }
}

// MODE 0: out = acc+bias -> split fp16 (Qh,Ql) row-major
// MODE 1: out = acc+bias -> hi fp16, transposed [e][seq] (V)
// MODE 2: out = acc*scale -> fp32 row-major (S, O)
// MODE 3: out = acc+bias -> hi fp16 row-major (K)
template <int MODE>
__global__ __launch_bounds__(256, 1)
void gemm_f16x2(const __half* __restrict__ Ah, const __half* __restrict__ Al,
                const __half* __restrict__ Bh,
                int lda, int ldb, long long sA, long long sB, int Kd,
                const float* __restrict__ bias, float scale,
                float* __restrict__ out32, int ldc, long long sC,
                __half* __restrict__ outh, __half* __restrict__ outl)
{
    extern __shared__ __align__(128) char smem[];
    const unsigned sbase = smem_u32(smem);
    const int tid = threadIdx.x;
    const int bz  = blockIdx.z;

    Ah += (size_t)bz * sA;  Al += (size_t)bz * sA;
    Bh += (size_t)bz * sB;

    const int m0 = blockIdx.x * 128;
    const int n0 = blockIdx.y * 128;

    const __half* a_h = Ah + (size_t)m0 * lda;
    const __half* a_l = Al + (size_t)m0 * lda;
    const __half* b_h = Bh + (size_t)n0 * ldb;

    const int lane = tid & 31;
    const int w    = tid >> 5;
    const int wm   = w & 1;         // 2 warps in M (64 rows each)
    const int wn   = w >> 1;        // 4 warps in N (32 cols each)

    const unsigned aoff = ((unsigned)(wm * 64 + (lane & 15)) << 6) + ((unsigned)(lane >> 4) << 4);
    const unsigned boff = ((unsigned)(wn * 32 + ((lane >> 4) << 3) + (lane & 7)) << 6)
                        + ((unsigned)((lane >> 3) & 1) << 4);

    float acc[4][4][4];
    #pragma unroll
    for (int i = 0; i < 4; ++i)
        #pragma unroll
        for (int j = 0; j < 4; ++j)
            #pragma unroll
            for (int q = 0; q < 4; ++q) acc[i][j][q] = 0.0f;

    const int NC = Kd / BKW;

    // prologue: stages 0..2
    #pragma unroll
    for (int p = 0; p < STAGES - 1; ++p) {
        const unsigned sb = sbase + p * STG_B;
        const int k0 = p * BKW;
        load_tile(sb,              a_h + k0, lda, tid);
        load_tile(sb + TBYTES,     a_l + k0, lda, tid);
        load_tile(sb + 2 * TBYTES, b_h + k0, ldb, tid);
        asm volatile("cp.async.commit_group;" ::: "memory");
    }

    for (int c = 0; c < NC; ++c) {
        if (c + STAGES - 1 < NC)
            asm volatile("cp.async.wait_group %0;" :: "n"(STAGES - 2) : "memory");
        else
            asm volatile("cp.async.wait_group %0;" :: "n"(0) : "memory");
        __syncthreads();

        if (c + STAGES - 1 < NC) {
            const unsigned sb = sbase + ((c + STAGES - 1) % STAGES) * STG_B;
            const int k0 = (c + STAGES - 1) * BKW;
            load_tile(sb,              a_h + k0, lda, tid);
            load_tile(sb + TBYTES,     a_l + k0, lda, tid);
            load_tile(sb + 2 * TBYTES, b_h + k0, ldb, tid);
            asm volatile("cp.async.commit_group;" ::: "memory");
        }

        const unsigned sb = sbase + (c % STAGES) * STG_B;
        #pragma unroll
        for (int ks = 0; ks < 2; ++ks) {
            unsigned Afh[4][4], Afl[4][4], Bfh[4][2];
            #pragma unroll
            for (int mt = 0; mt < 4; ++mt) {
                const unsigned o = swz(aoff + (mt << 10) + (ks << 5));
                ldm_x4(Afh[mt][0], Afh[mt][1], Afh[mt][2], Afh[mt][3], sb + o);
                ldm_x4(Afl[mt][0], Afl[mt][1], Afl[mt][2], Afl[mt][3], sb + TBYTES + o);
            }
            #pragma unroll
            for (int jp = 0; jp < 2; ++jp) {
                const unsigned o = swz(boff + (jp << 10) + (ks << 5));
                ldm_x4(Bfh[2*jp][0], Bfh[2*jp][1], Bfh[2*jp+1][0], Bfh[2*jp+1][1],
                       sb + 2 * TBYTES + o);
            }
            #pragma unroll
            for (int mt = 0; mt < 4; ++mt)
                #pragma unroll
                for (int nt = 0; nt < 4; ++nt) {
                    mma16816(acc[mt][nt], Afh[mt], Bfh[nt]);
                    mma16816(acc[mt][nt], Afl[mt], Bfh[nt]);
                }
        }
    }

    // ------------------------------ epilogue -------------------------------
    const int g  = lane >> 2;            // row within 8
    const int tg = lane & 3;             // col pair
    #pragma unroll
    for (int mt = 0; mt < 4; ++mt) {
        #pragma unroll
        for (int nt = 0; nt < 4; ++nt) {
            const int nb = n0 + wn * 32 + nt * 8 + 2 * tg;
            const int mb = m0 + wm * 64 + mt * 16 + g;
            float v0 = acc[mt][nt][0], v1 = acc[mt][nt][1];
            float v2 = acc[mt][nt][2], v3 = acc[mt][nt][3];
            if (MODE == 2) {
                float* d0 = out32 + (size_t)bz * sC + (size_t)mb * ldc + nb;
                float* d1 = out32 + (size_t)bz * sC + (size_t)(mb + 8) * ldc + nb;
                *(float2*)d0 = make_float2(v0 * scale, v1 * scale);
                *(float2*)d1 = make_float2(v2 * scale, v3 * scale);
            } else {
                const float b0 = bias[nb], b1 = bias[nb + 1];
                if (MODE == 0) {
                    unsigned short h0, l0, h1, l1, h2, l2, h3, l3;
                    hsplit(v0 + b0, h0, l0); hsplit(v1 + b1, h1, l1);
                    hsplit(v2 + b0, h2, l2); hsplit(v3 + b1, h3, l3);
                    const size_t o0 = (size_t)mb * ldc + nb;
                    const size_t o1 = (size_t)(mb + 8) * ldc + nb;
                    *(unsigned*)(outh + o0) = ((unsigned)h1 << 16) | h0;
                    *(unsigned*)(outl + o0) = ((unsigned)l1 << 16) | l0;
                    *(unsigned*)(outh + o1) = ((unsigned)h3 << 16) | h2;
                    *(unsigned*)(outl + o1) = ((unsigned)l3 << 16) | l2;
                } else if (MODE == 3) {
                    const unsigned short h0 = hhi(v0 + b0), h1 = hhi(v1 + b1);
                    const unsigned short h2 = hhi(v2 + b0), h3 = hhi(v3 + b1);
                    const size_t o0 = (size_t)mb * ldc + nb;
                    const size_t o1 = (size_t)(mb + 8) * ldc + nb;
                    *(unsigned*)(outh + o0) = ((unsigned)h1 << 16) | h0;
                    *(unsigned*)(outh + o1) = ((unsigned)h3 << 16) | h2;
                } else {            // MODE 1: transposed [e][seq]
                    const int b2 = mb >> 12;
                    const int s0 = mb & (SEQ - 1);
                    const size_t base = (size_t)b2 * DIM * SEQ;
                    outh[base + (size_t)nb * SEQ + s0]           = __ushort_as_half(hhi(v0 + b0));
                    outh[base + (size_t)(nb + 1) * SEQ + s0]     = __ushort_as_half(hhi(v1 + b1));
                    outh[base + (size_t)nb * SEQ + s0 + 8]       = __ushort_as_half(hhi(v2 + b0));
                    outh[base + (size_t)(nb + 1) * SEQ + s0 + 8] = __ushort_as_half(hhi(v3 + b1));
                }
            }
        }
    }
}

// ------------------------- conversion kernels ------------------------------
__global__ __launch_bounds__(256)
void split_f32_kernel(const float* __restrict__ x,
                      __half* __restrict__ h, __half* __restrict__ l)
{
    const size_t i = (size_t)blockIdx.x * 256 + threadIdx.x;
    const float4 v = ((const float4*)x)[i];
    unsigned short h0, l0, h1, l1, h2, l2, h3, l3;
    hsplit(v.x, h0, l0); hsplit(v.y, h1, l1); hsplit(v.z, h2, l2); hsplit(v.w, h3, l3);
    ((uint2*)h)[i] = make_uint2(((unsigned)h1 << 16) | h0, ((unsigned)h3 << 16) | h2);
    ((uint2*)l)[i] = make_uint2(((unsigned)l1 << 16) | l0, ((unsigned)l3 << 16) | l2);
}

__global__ __launch_bounds__(256)
void transpose_hi_kernel(const float* __restrict__ W, __half* __restrict__ Th)
{
    __shared__ float t[32][33];
    const int k0 = blockIdx.x * 32, n0 = blockIdx.y * 32;
    const int c = threadIdx.x & 31, r0 = threadIdx.x >> 5;
    #pragma unroll
    for (int i = 0; i < 4; ++i)
        t[r0 + i * 8][c] = W[(size_t)(k0 + r0 + i * 8) * DIM + n0 + c];
    __syncthreads();
    #pragma unroll
    for (int i = 0; i < 4; ++i) {
        const int r = r0 + i * 8;
        Th[(size_t)(n0 + r) * DIM + k0 + c] = __ushort_as_half(hhi(t[c][r]));
    }
}

// ------------------------------ softmax ------------------------------------
__global__ __launch_bounds__(256)
void softmax_split_kernel(const float* __restrict__ S,
                          __half* __restrict__ Ph, __half* __restrict__ Pl)
{
    const float* p = S + (size_t)blockIdx.x * SEQ;
    const int tid = threadIdx.x;

    float4 v[4];
    float mx = -INFINITY;
    #pragma unroll
    for (int i = 0; i < 4; ++i) {
        v[i] = ((const float4*)p)[tid + i * 256];
        mx = fmaxf(mx, fmaxf(fmaxf(v[i].x, v[i].y), fmaxf(v[i].z, v[i].w)));
    }
    #pragma unroll
    for (int o = 16; o > 0; o >>= 1)
        mx = fmaxf(mx, __shfl_xor_sync(0xFFFFFFFFu, mx, o));

    __shared__ float redmx[8], redsm[8];
    if ((tid & 31) == 0) redmx[tid >> 5] = mx;
    __syncthreads();
    mx = redmx[0];
    #pragma unroll
    for (int w = 1; w < 8; ++w) mx = fmaxf(mx, redmx[w]);

    float sum = 0.0f;
    #pragma unroll
    for (int i = 0; i < 4; ++i) {
        v[i].x = __expf(v[i].x - mx); v[i].y = __expf(v[i].y - mx);
        v[i].z = __expf(v[i].z - mx); v[i].w = __expf(v[i].w - mx);
        sum += (v[i].x + v[i].y) + (v[i].z + v[i].w);
    }
    #pragma unroll
    for (int o = 16; o > 0; o >>= 1)
        sum += __shfl_xor_sync(0xFFFFFFFFu, sum, o);
    if ((tid & 31) == 0) redsm[tid >> 5] = sum;
    __syncthreads();
    sum = 0.0f;
    #pragma unroll
    for (int w = 0; w < 8; ++w) sum += redsm[w];
    const float inv = 1.0f / sum;

    #pragma unroll
    for (int i = 0; i < 4; ++i) {
        unsigned short h0, l0, h1, l1, h2, l2, h3, l3;
        hsplit(v[i].x * inv, h0, l0); hsplit(v[i].y * inv, h1, l1);
        hsplit(v[i].z * inv, h2, l2); hsplit(v[i].w * inv, h3, l3);
        const size_t q = (size_t)blockIdx.x * (SEQ / 4) + tid + i * 256;
        ((uint2*)Ph)[q] = make_uint2(((unsigned)h1 << 16) | h0, ((unsigned)h3 << 16) | h2);
        ((uint2*)Pl)[q] = make_uint2(((unsigned)l1 << 16) | l0, ((unsigned)l3 << 16) | l2);
    }
}

// ------------------------------ launch -------------------------------------
extern "C" void kernel_launch(void* const* d_in, const int* in_sizes, int n_in,
                              void* d_out, int out_size)
{
    const float* X  = (const float*)d_in[0];
    const float* Wq = (const float*)d_in[1];
    const float* Wk = (const float*)d_in[2];
    const float* Wv = (const float*)d_in[3];
    const float* bq = (const float*)d_in[4];
    const float* bk = (const float*)d_in[5];
    const float* bv = (const float*)d_in[6];
    float* O = (float*)d_out;

    __half *Xh, *Xl, *Wt, *Qh, *Ql, *Kh, *Vt, *Ph, *Pl;
    float* S;
    cudaGetSymbolAddress((void**)&Xh, g_Xh);
    cudaGetSymbolAddress((void**)&Xl, g_Xl);
    cudaGetSymbolAddress((void**)&Wt, g_Wt);
    cudaGetSymbolAddress((void**)&Qh, g_Qh);
    cudaGetSymbolAddress((void**)&Ql, g_Ql);
    cudaGetSymbolAddress((void**)&Kh, g_Kh);
    cudaGetSymbolAddress((void**)&Vt, g_Vt);
    cudaGetSymbolAddress((void**)&S,  g_S);
    cudaGetSymbolAddress((void**)&Ph, g_Ph);
    cudaGetSymbolAddress((void**)&Pl, g_Pl);

    cudaFuncSetAttribute(gemm_f16x2<0>, cudaFuncAttributeMaxDynamicSharedMemorySize, GEMM_SMEM);
    cudaFuncSetAttribute(gemm_f16x2<1>, cudaFuncAttributeMaxDynamicSharedMemorySize, GEMM_SMEM);
    cudaFuncSetAttribute(gemm_f16x2<2>, cudaFuncAttributeMaxDynamicSharedMemorySize, GEMM_SMEM);
    cudaFuncSetAttribute(gemm_f16x2<3>, cudaFuncAttributeMaxDynamicSharedMemorySize, GEMM_SMEM);

    const size_t DD = (size_t)DIM * DIM;

    // 0) conversions
    split_f32_kernel<<<(M_TOT * DIM) / (4 * 256), 256>>>(X, Xh, Xl);
    transpose_hi_kernel<<<dim3(32, 32), 256>>>(Wq, Wt + 0 * DD);
    transpose_hi_kernel<<<dim3(32, 32), 256>>>(Wk, Wt + 1 * DD);
    transpose_hi_kernel<<<dim3(32, 32), 256>>>(Wv, Wt + 2 * DD);

    // 1) projections: [16384,1024] x Wt[n][k]
    {
        dim3 g(M_TOT / 128, DIM / 128, 1);       // (128, 8)
        gemm_f16x2<0><<<g, 256, GEMM_SMEM>>>(Xh, Xl, Wt + 0 * DD,
            DIM, DIM, 0, 0, DIM, bq, 1.0f, nullptr, DIM, 0, Qh, Ql);
        gemm_f16x2<3><<<g, 256, GEMM_SMEM>>>(Xh, Xl, Wt + 1 * DD,
            DIM, DIM, 0, 0, DIM, bk, 1.0f, nullptr, DIM, 0, Kh, nullptr);
        gemm_f16x2<1><<<g, 256, GEMM_SMEM>>>(Xh, Xl, Wt + 2 * DD,
            DIM, DIM, 0, 0, DIM, bv, 1.0f, nullptr, DIM, 0, Vt, nullptr);
    }

    // 2) S = (Q K^T)/32
    {
        dim3 g(SEQ / 128, SEQ / 128, BATCH);     // (32, 32, 4)
        gemm_f16x2<2><<<g, 256, GEMM_SMEM>>>(Qh, Ql, Kh,
            DIM, DIM, (long long)SEQ * DIM, (long long)SEQ * DIM, DIM,
            nullptr, 1.0f / 32.0f, S, SEQ, (long long)SEQ * SEQ, nullptr, nullptr);
    }

    // 3) softmax rows -> split P
    softmax_split_kernel<<<BATCH * SEQ, 256>>>(S, Ph, Pl);

    // 4) O = P V
    {
        dim3 g(SEQ / 128, DIM / 128, BATCH);     // (32, 8, 4)
        gemm_f16x2<2><<<g, 256, GEMM_SMEM>>>(Ph, Pl, Vt,
            SEQ, SEQ, (long long)SEQ * SEQ, (long long)DIM * SEQ, SEQ,
            nullptr, 1.0f, O, DIM, (long long)SEQ * DIM, nullptr, nullptr);
    }
}